// round 5
// baseline (speedup 1.0000x reference)
#include <cuda_runtime.h>
#include <math.h>
#include <stdint.h>

#define SEQ   4096
#define DIM   1024
#define OUTD  2048
#define SCALE 0.03125f   // 1/sqrt(1024)

#define PADW  36                        // 32 floats + 4 pad per smem row
#define ABUF  (128 * PADW * 4)          // A tile: 18432 B
#define BBUF  (256 * PADW * 4)          // B tile: 36864 B
#define STAGE (ABUF + BBUF)             // 55296 B
#define SMEM_DYN (2 * STAGE)            // 110592 B

// ---------------------------------------------------------------------------
// scratch (__device__ globals; no allocations allowed)
// ---------------------------------------------------------------------------
__device__ float g_x [(size_t)SEQ * DIM];          // x, tf32-rounded
__device__ float g_wt[(size_t)3 * DIM * DIM];      // W^T (Q,K,V), tf32-rounded
__device__ float g_q [(size_t)SEQ * DIM];          // tf32-rounded
__device__ float g_k [(size_t)SEQ * DIM];          // tf32-rounded
__device__ float g_vt[(size_t)DIM * SEQ];          // V^T [d][s], tf32-rounded
__device__ float g_s [(size_t)SEQ * SEQ];          // scores fp32
__device__ float g_p [(size_t)SEQ * SEQ];          // probs, tf32-rounded

// ---------------------------------------------------------------------------
// helpers
// ---------------------------------------------------------------------------
__device__ __forceinline__ uint32_t smem_u32(const void* p) {
    uint32_t a;
    asm("{ .reg .u64 t; cvta.to.shared.u64 t, %1; cvt.u32.u64 %0, t; }" : "=r"(a) : "l"(p));
    return a;
}
__device__ __forceinline__ float tf32r(float x) {
    uint32_t u;
    asm("cvt.rna.tf32.f32 %0, %1;" : "=r"(u) : "f"(x));
    return __uint_as_float(u);
}
__device__ __forceinline__ void cp16(uint32_t s, const float* g) {
    asm volatile("{ .reg .u64 gg; cvta.to.global.u64 gg, %1;"
                 "  cp.async.cg.shared.global [%0], [gg], 16; }"
                 :: "r"(s), "l"(g));
}
#define CP_COMMIT() asm volatile("cp.async.commit_group;" ::: "memory")
#define CP_WAIT1()  asm volatile("cp.async.wait_group 1;"  ::: "memory")

__device__ __forceinline__ void mma8(float* d, const float* a, const float* b) {
    asm volatile(
        "mma.sync.aligned.m16n8k8.row.col.f32.tf32.tf32.f32 "
        "{%0,%1,%2,%3}, {%4,%5,%6,%7}, {%8,%9}, {%0,%1,%2,%3};"
        : "+f"(d[0]), "+f"(d[1]), "+f"(d[2]), "+f"(d[3])
        : "r"(__float_as_uint(a[0])), "r"(__float_as_uint(a[1])),
          "r"(__float_as_uint(a[2])), "r"(__float_as_uint(a[3])),
          "r"(__float_as_uint(b[0])), "r"(__float_as_uint(b[1])));
}

// ---------------------------------------------------------------------------
// mainloop: acc[4][8][4] += A[128,K] * B[256,K]^T over k in [kbeg,kend)
// A: [m][k] row-major (lda), rows arow0.. ; B: [n][k] row-major (ldb), rows brow0..
// 8 warps = 2(m) x 4(n); warp tile 64x64; m16n8k8 tf32, 4x8 tiles/warp
// ---------------------------------------------------------------------------
__device__ __forceinline__ void gemm_mainloop(
    float acc[4][8][4], char* smem,
    const float* __restrict__ Ag, int lda, int arow0,
    const float* __restrict__ Bg, int ldb, int brow0,
    int kbeg, int kend)
{
    const int tid  = threadIdx.x;
    const int wid  = tid >> 5, lane = tid & 31;
    const int wm   = (wid & 1) * 64;
    const int wn   = (wid >> 1) * 64;
    const int r    = lane >> 2, cc = lane & 3;
    const uint32_t sA = smem_u32(smem);
    const int nch  = (kend - kbeg) >> 5;

    const int alm = tid >> 1;            // A loader: row (2 threads/row)
    const int alq = (tid & 1) * 4;       // A loader: 16B-chunk start
    const int blm = tid;                 // B loader: one row per thread

#define ISSUE_CHUNK(stg, k0) do {                                              \
    uint32_t _st = sA + (stg) * STAGE;                                         \
    _Pragma("unroll")                                                          \
    for (int q = 0; q < 4; q++)                                                \
        cp16(_st + (alm * PADW + (alq + q) * 4) * 4,                           \
             Ag + (size_t)(arow0 + alm) * lda + (k0) + (alq + q) * 4);         \
    _Pragma("unroll")                                                          \
    for (int q = 0; q < 8; q++)                                                \
        cp16(_st + ABUF + (blm * PADW + q * 4) * 4,                            \
             Bg + (size_t)(brow0 + blm) * ldb + (k0) + q * 4);                 \
} while (0)

    // prologue: fill both stages
    ISSUE_CHUNK(0, kbeg);
    CP_COMMIT();
    if (nch > 1) ISSUE_CHUNK(1, kbeg + 32);
    CP_COMMIT();

    for (int c = 0; c < nch; c++) {
        CP_WAIT1();
        __syncthreads();
        const float* As = (const float*)(smem + (c & 1) * STAGE);
        const float* Bs = (const float*)(smem + (c & 1) * STAGE + ABUF);
#pragma unroll
        for (int ks = 0; ks < 4; ks++) {
            float a[4][4], b[8][2];
#pragma unroll
            for (int mt = 0; mt < 4; mt++) {
                const float* p = As + (wm + mt * 16 + r) * PADW + ks * 8 + cc;
                a[mt][0] = p[0];
                a[mt][1] = p[8 * PADW];
                a[mt][2] = p[4];
                a[mt][3] = p[8 * PADW + 4];
            }
#pragma unroll
            for (int nt = 0; nt < 8; nt++) {
                const float* p = Bs + (wn + nt * 8 + r) * PADW + ks * 8 + cc;
                b[nt][0] = p[0];
                b[nt][1] = p[4];
            }
#pragma unroll
            for (int mt = 0; mt < 4; mt++)
#pragma unroll
                for (int nt = 0; nt < 8; nt++)
                    mma8(acc[mt][nt], a[mt], b[nt]);
        }
        __syncthreads();
        if (c + 2 < nch) ISSUE_CHUNK(c & 1, kbeg + (c + 2) * 32);
        CP_COMMIT();
    }
#undef ISSUE_CHUNK
}

#define GEMM_THREAD_COORDS()                                   \
    const int tid = threadIdx.x;                               \
    const int wid = tid >> 5, lane = tid & 31;                 \
    const int wm = (wid & 1) * 64, wn = (wid >> 1) * 64;       \
    const int r = lane >> 2, cc = lane & 3;

#define ZERO_ACC(acc)                                          \
    float acc[4][8][4];                                        \
    _Pragma("unroll")                                          \
    for (int i = 0; i < 4; i++)                                \
        _Pragma("unroll")                                      \
        for (int j = 0; j < 8; j++)                            \
            _Pragma("unroll")                                  \
            for (int q = 0; q < 4; q++) acc[i][j][q] = 0.f;

// ---------------------------------------------------------------------------
// QKV: z=0: Q = x@Wq' + bq ; z=1: K ; z=2: V^T = Wvt @ x^T + bv(row)
// grid (128, 1, 3): z<2 -> bi=b>>2 (32 row tiles), bj=b&3 (4 col tiles of 256)
//                   z=2 -> bi=b>>4 (8 row tiles over DIM), bj=b&15 (16 over SEQ)
// ---------------------------------------------------------------------------
__global__ __launch_bounds__(256, 1) void gemm_qkv_kernel(
    const float* __restrict__ bq, const float* __restrict__ bk, const float* __restrict__ bv)
{
    const int z = blockIdx.z;
    extern __shared__ char smem[];
    const int b = blockIdx.x;
    const int row0 = (z == 2 ? (b >> 4) : (b >> 2)) * 128;
    const int col0 = (z == 2 ? (b & 15) : (b & 3)) * 256;

    ZERO_ACC(acc);

    const float *Ag, *Bg, *bias;
    if (z == 0)      { Ag = g_x;                  Bg = g_wt;             bias = bq; }
    else if (z == 1) { Ag = g_x;                  Bg = g_wt + DIM * DIM; bias = bk; }
    else             { Ag = g_wt + 2 * DIM * DIM; Bg = g_x;              bias = bv; }

    gemm_mainloop(acc, smem, Ag, DIM, row0, Bg, DIM, col0, 0, DIM);

    GEMM_THREAD_COORDS();
    float* dst; size_t ld;
    if (z == 0)      { dst = g_q;  ld = DIM; }
    else if (z == 1) { dst = g_k;  ld = DIM; }
    else             { dst = g_vt; ld = SEQ; }

#pragma unroll
    for (int mt = 0; mt < 4; mt++)
#pragma unroll
        for (int h = 0; h < 2; h++) {
            int m = row0 + wm + mt * 16 + r + 8 * h;
            float brow = (z == 2) ? bias[m] : 0.f;
#pragma unroll
            for (int nt = 0; nt < 8; nt++) {
                int n = col0 + wn + nt * 8 + 2 * cc;
                float v0 = acc[mt][nt][2 * h + 0] + ((z == 2) ? brow : bias[n]);
                float v1 = acc[mt][nt][2 * h + 1] + ((z == 2) ? brow : bias[n + 1]);
                float2 w = make_float2(tf32r(v0), tf32r(v1));
                *(float2*)&dst[(size_t)m * ld + n] = w;
            }
        }
}

// ---------------------------------------------------------------------------
// scores: S = SCALE * Q K^T, tiles 128x256; keep tile iff 2*bj2+1 >= bi (272)
// ---------------------------------------------------------------------------
__global__ __launch_bounds__(256, 1) void gemm_scores_kernel()
{
    int bi = 0, rem = blockIdx.x;
    while (rem >= 16 - (bi >> 1)) { rem -= 16 - (bi >> 1); bi++; }
    const int bj2 = (bi >> 1) + rem;

    extern __shared__ char smem[];
    const int row0 = bi * 128, col0 = bj2 * 256;

    ZERO_ACC(acc);
    gemm_mainloop(acc, smem, g_q, DIM, row0, g_k, DIM, col0, 0, DIM);

    GEMM_THREAD_COORDS();
#pragma unroll
    for (int mt = 0; mt < 4; mt++)
#pragma unroll
        for (int h = 0; h < 2; h++) {
            int m = row0 + wm + mt * 16 + r + 8 * h;
#pragma unroll
            for (int nt = 0; nt < 8; nt++) {
                int n = col0 + wn + nt * 8 + 2 * cc;
                float2 w = make_float2(acc[mt][nt][2 * h] * SCALE,
                                       acc[mt][nt][2 * h + 1] * SCALE);
                *(float2*)&g_s[(size_t)m * SEQ + n] = w;
            }
        }
}

// ---------------------------------------------------------------------------
// softmax over j >= i; writes tf32-rounded probs, zero strip in diagonal tile
// ---------------------------------------------------------------------------
__global__ __launch_bounds__(256) void softmax_kernel()
{
    const int i = blockIdx.x;
    const int t = threadIdx.x;
    const float* row = g_s + (size_t)i * SEQ;

    float vals[16];
    float m = -INFINITY;
#pragma unroll
    for (int c = 0; c < 16; c++) {
        int j = t + (c << 8);
        float v = (j >= i) ? row[j] : -INFINITY;
        vals[c] = v;
        m = fmaxf(m, v);
    }
    __shared__ float red[8];
#pragma unroll
    for (int o = 16; o > 0; o >>= 1) m = fmaxf(m, __shfl_xor_sync(0xffffffffu, m, o));
    if ((t & 31) == 0) red[t >> 5] = m;
    __syncthreads();
    float mm = red[0];
#pragma unroll
    for (int w = 1; w < 8; w++) mm = fmaxf(mm, red[w]);
    __syncthreads();

    float sum = 0.f;
#pragma unroll
    for (int c = 0; c < 16; c++) {
        float e = (vals[c] > -INFINITY) ? __expf(vals[c] - mm) : 0.f;
        vals[c] = e;
        sum += e;
    }
#pragma unroll
    for (int o = 16; o > 0; o >>= 1) sum += __shfl_xor_sync(0xffffffffu, sum, o);
    if ((t & 31) == 0) red[t >> 5] = sum;
    __syncthreads();
    float tot = 0.f;
#pragma unroll
    for (int w = 0; w < 8; w++) tot += red[w];
    const float inv = 1.0f / tot;

    const int rowstart = i & ~127;
    float* p = g_p + (size_t)i * SEQ;
#pragma unroll
    for (int c = 0; c < 16; c++) {
        int j = t + (c << 8);
        if (j >= i)             p[j] = tf32r(vals[c] * inv);
        else if (j >= rowstart) p[j] = 0.f;
    }
}

// ---------------------------------------------------------------------------
// PV: read = P @ V ; A = probs [s][s], B = V^T [d][s]; k starts at diagonal
// grid (4, 32): col0 = x*256, row0 = y*128
// ---------------------------------------------------------------------------
__global__ __launch_bounds__(256, 1) void gemm_pv_kernel(float* __restrict__ out)
{
    extern __shared__ char smem[];
    const int row0 = blockIdx.y * 128, col0 = blockIdx.x * 256;

    ZERO_ACC(acc);
    gemm_mainloop(acc, smem, g_p, SEQ, row0, g_vt, SEQ, col0, row0, SEQ);

    GEMM_THREAD_COORDS();
#pragma unroll
    for (int mt = 0; mt < 4; mt++)
#pragma unroll
        for (int h = 0; h < 2; h++) {
            int m = row0 + wm + mt * 16 + r + 8 * h;
#pragma unroll
            for (int nt = 0; nt < 8; nt++) {
                int n = col0 + wn + nt * 8 + 2 * cc;
                float2 w = make_float2(acc[mt][nt][2 * h], acc[mt][nt][2 * h + 1]);
                *(float2*)&out[(size_t)m * OUTD + DIM + n] = w;
            }
        }
}

// ---------------------------------------------------------------------------
// conversions
// ---------------------------------------------------------------------------
__global__ __launch_bounds__(256) void conv_x_kernel(const float* __restrict__ x,
                                                     float* __restrict__ out)
{
    int idx = blockIdx.x * 256 + threadIdx.x;   // float4 index
    int r = idx >> 8;
    int c = (idx & 255) * 4;
    float4 v = *(const float4*)&x[(size_t)r * DIM + c];
    *(float4*)&out[(size_t)r * OUTD + c] = v;   // out[:, 0:1024] = x
    float4 w = make_float4(tf32r(v.x), tf32r(v.y), tf32r(v.z), tf32r(v.w));
    *(float4*)&g_x[(size_t)r * DIM + c] = w;
}

// transpose + tf32-round W [k][n] -> Wt [n][k] (slot z: 0=Q, 1=K, 2=V)
__global__ __launch_bounds__(256) void conv_w_kernel(const float* __restrict__ Wq,
                                                     const float* __restrict__ Wk,
                                                     const float* __restrict__ Wv)
{
    __shared__ float t[32][33];
    const int z = blockIdx.z;
    const float* W = (z == 0) ? Wq : (z == 1) ? Wk : Wv;
    const int n0 = blockIdx.x * 32, k0 = blockIdx.y * 32;
    const int tx = threadIdx.x & 31, ty = threadIdx.x >> 5;
#pragma unroll
    for (int i = 0; i < 4; i++) {
        int k = ty + i * 8;
        t[k][tx] = W[(size_t)(k0 + k) * DIM + n0 + tx];
    }
    __syncthreads();
    float* T = g_wt + (size_t)z * DIM * DIM;
#pragma unroll
    for (int i = 0; i < 4; i++) {
        int n = ty + i * 8;
        T[(size_t)(n0 + n) * DIM + k0 + tx] = tf32r(t[tx][n]);
    }
}

// ---------------------------------------------------------------------------
extern "C" void kernel_launch(void* const* d_in, const int* in_sizes, int n_in,
                              void* d_out, int out_size)
{
    const float* x  = (const float*)d_in[0];
    const float* Wk = (const float*)d_in[1];
    const float* bk = (const float*)d_in[2];
    const float* Wq = (const float*)d_in[3];
    const float* bq = (const float*)d_in[4];
    const float* Wv = (const float*)d_in[5];
    const float* bv = (const float*)d_in[6];
    float* out = (float*)d_out;

    cudaFuncSetAttribute(gemm_qkv_kernel,    cudaFuncAttributeMaxDynamicSharedMemorySize, SMEM_DYN);
    cudaFuncSetAttribute(gemm_scores_kernel, cudaFuncAttributeMaxDynamicSharedMemorySize, SMEM_DYN);
    cudaFuncSetAttribute(gemm_pv_kernel,     cudaFuncAttributeMaxDynamicSharedMemorySize, SMEM_DYN);

    conv_x_kernel<<<4096, 256>>>(x, out);
    conv_w_kernel<<<dim3(32, 32, 3), 256>>>(Wq, Wk, Wv);
    gemm_qkv_kernel<<<dim3(128, 1, 3), 256, SMEM_DYN>>>(bq, bk, bv);
    gemm_scores_kernel<<<272, 256, SMEM_DYN>>>();
    softmax_kernel<<<SEQ, 256>>>();
    gemm_pv_kernel<<<dim3(4, 32), 256, SMEM_DYN>>>(out);
}

// round 6
// speedup vs baseline: 1.6015x; 1.6015x over previous
#include <cuda_runtime.h>
#include <math.h>
#include <stdint.h>

#define SEQ   4096
#define DIM   1024
#define OUTD  2048
#define SCALE 0.03125f   // 1/sqrt(1024)

#define PADW  36                        // 32 floats + 4 pad per smem row
#define BROWS 128
#define BBUF  (BROWS * PADW * 4)        // 18432 B

// ---------------------------------------------------------------------------
// scratch (__device__ globals; no allocations allowed)
// ---------------------------------------------------------------------------
__device__ float g_x [(size_t)SEQ * DIM];          // x, tf32-rounded
__device__ float g_wt[(size_t)3 * DIM * DIM];      // W^T (Q,K,V), tf32-rounded
__device__ float g_q [(size_t)SEQ * DIM];          // tf32-rounded
__device__ float g_k [(size_t)SEQ * DIM];          // tf32-rounded
__device__ float g_vt[(size_t)DIM * SEQ];          // V^T [d][s], tf32-rounded
__device__ float g_s [(size_t)SEQ * SEQ];          // scores fp32
__device__ float g_p [(size_t)SEQ * SEQ];          // probs, tf32-rounded

// ---------------------------------------------------------------------------
// helpers
// ---------------------------------------------------------------------------
__device__ __forceinline__ uint32_t smem_u32(const void* p) {
    uint32_t a;
    asm("{ .reg .u64 t; cvta.to.shared.u64 t, %1; cvt.u32.u64 %0, t; }" : "=r"(a) : "l"(p));
    return a;
}
__device__ __forceinline__ float tf32r(float x) {
    uint32_t u;
    asm("cvt.rna.tf32.f32 %0, %1;" : "=r"(u) : "f"(x));
    return __uint_as_float(u);
}
__device__ __forceinline__ void cp16(uint32_t s, const float* g) {
    asm volatile("{ .reg .u64 gg; cvta.to.global.u64 gg, %1;"
                 "  cp.async.cg.shared.global [%0], [gg], 16; }"
                 :: "r"(s), "l"(g));
}
#define CP_COMMIT() asm volatile("cp.async.commit_group;" ::: "memory")
#define CP_WAIT1()  asm volatile("cp.async.wait_group 1;"  ::: "memory")

__device__ __forceinline__ void ldsm4(uint32_t& r0, uint32_t& r1, uint32_t& r2, uint32_t& r3,
                                      uint32_t addr) {
    asm volatile("ldmatrix.sync.aligned.m8n8.x4.shared.b16 {%0,%1,%2,%3}, [%4];"
                 : "=r"(r0), "=r"(r1), "=r"(r2), "=r"(r3) : "r"(addr));
}

__device__ __forceinline__ void mma8(float* d, const uint32_t* a, const uint32_t* b) {
    asm volatile(
        "mma.sync.aligned.m16n8k8.row.col.f32.tf32.tf32.f32 "
        "{%0,%1,%2,%3}, {%4,%5,%6,%7}, {%8,%9}, {%0,%1,%2,%3};"
        : "+f"(d[0]), "+f"(d[1]), "+f"(d[2]), "+f"(d[3])
        : "r"(a[0]), "r"(a[1]), "r"(a[2]), "r"(a[3]), "r"(b[0]), "r"(b[1]));
}

// ---------------------------------------------------------------------------
// mainloop (512 threads): acc[MT][4][4] += A[MT*64,K] * B[128,K]^T
// 16 warps = 4(m) x 4(n); warp tile (MT*16)x32; tf32 m16n8k8; ldmatrix frags.
// A: [m][k] row-major (lda), rows arow0.. ; B: [n][k] row-major (ldb), brow0..
// ---------------------------------------------------------------------------
template <int MT>
__device__ __forceinline__ void gemm_mainloop(
    float (*acc)[4][4], char* smem,
    const float* __restrict__ Ag, int lda, int arow0,
    const float* __restrict__ Bg, int ldb, int brow0,
    int kbeg, int kend)
{
    constexpr int AROWS  = MT * 64;
    constexpr int ABUF   = AROWS * PADW * 4;
    constexpr int STAGEB = ABUF + BBUF;

    const int tid  = threadIdx.x;
    const int wid  = tid >> 5, lane = tid & 31;
    const int wm   = (wid & 3) * (MT * 16);
    const int wn   = (wid >> 2) * 32;
    const uint32_t sA = smem_u32(smem);
    const int nch  = (kend - kbeg) >> 5;

    // ldmatrix per-lane base offsets (bytes, within stage)
    const uint32_t aoff = ((wm + (lane & 15)) * PADW + (lane >> 4) * 4) * 4;
    const uint32_t boff = ABUF +
        ((wn + (lane & 7) + ((lane >> 4) & 1) * 8) * PADW + ((lane >> 3) & 1) * 4) * 4;

    // loaders
    const int ach = (MT == 4) ? 4 : 2;                 // A cp16 per thread
    const int alm = (MT == 4) ? (tid >> 1) : (tid >> 2);
    const int alq = (MT == 4) ? ((tid & 1) * 4) : ((tid & 3) * 2);
    const int blm = tid >> 2;
    const int blq = (tid & 3) * 2;

#define ISSUE_CHUNK(stg, k0) do {                                              \
    uint32_t _st = sA + (stg) * STAGEB;                                        \
    _Pragma("unroll")                                                          \
    for (int q = 0; q < ach; q++)                                              \
        cp16(_st + (alm * PADW + (alq + q) * 4) * 4,                           \
             Ag + (size_t)(arow0 + alm) * lda + (k0) + (alq + q) * 4);         \
    _Pragma("unroll")                                                          \
    for (int q = 0; q < 2; q++)                                                \
        cp16(_st + ABUF + (blm * PADW + (blq + q) * 4) * 4,                    \
             Bg + (size_t)(brow0 + blm) * ldb + (k0) + (blq + q) * 4);         \
} while (0)

    ISSUE_CHUNK(0, kbeg);
    CP_COMMIT();
    if (nch > 1) ISSUE_CHUNK(1, kbeg + 32);
    CP_COMMIT();

    for (int c = 0; c < nch; c++) {
        CP_WAIT1();
        __syncthreads();
        const uint32_t sb = sA + (c & 1) * STAGEB;
#pragma unroll
        for (int ks = 0; ks < 4; ks++) {
            uint32_t af[MT][4], bf[4][2];
#pragma unroll
            for (int mt = 0; mt < MT; mt++)
                ldsm4(af[mt][0], af[mt][1], af[mt][2], af[mt][3],
                      sb + aoff + mt * (16 * PADW * 4) + ks * 32);
            ldsm4(bf[0][0], bf[0][1], bf[1][0], bf[1][1], sb + boff + ks * 32);
            ldsm4(bf[2][0], bf[2][1], bf[3][0], bf[3][1],
                  sb + boff + 16 * PADW * 4 + ks * 32);
#pragma unroll
            for (int mt = 0; mt < MT; mt++)
#pragma unroll
                for (int nt = 0; nt < 4; nt++)
                    mma8(acc[mt][nt], af[mt], bf[nt]);
        }
        __syncthreads();
        if (c + 2 < nch) ISSUE_CHUNK(c & 1, kbeg + (c + 2) * 32);
        CP_COMMIT();
    }
#undef ISSUE_CHUNK
}

#define GEMM_THREAD_COORDS(MT)                                   \
    const int tid = threadIdx.x;                                 \
    const int wid = tid >> 5, lane = tid & 31;                   \
    const int wm = (wid & 3) * ((MT) * 16), wn = (wid >> 2) * 32;\
    const int r = lane >> 2, cc = lane & 3;

#define ZERO_ACC(acc, MT)                                        \
    float acc[MT][4][4];                                         \
    _Pragma("unroll")                                            \
    for (int i = 0; i < MT; i++)                                 \
        _Pragma("unroll")                                        \
        for (int j = 0; j < 4; j++)                              \
            _Pragma("unroll")                                    \
            for (int q = 0; q < 4; q++) acc[i][j][q] = 0.f;

// ---------------------------------------------------------------------------
// QKV: z=0: Q = x@Wq' + bq ; z=1: K ; z=2: V^T = Wvt @ x^T + bv(row)
// grid (128,1,3): z<2: bi=b>>3 (16 m-tiles of 256), bj=b&7 (8 n-tiles of 128)
//                 z=2: bi=b>>5 (4 m-tiles over DIM), bj=b&31 (32 over SEQ)
// ---------------------------------------------------------------------------
__global__ __launch_bounds__(512, 1) void gemm_qkv_kernel(
    const float* __restrict__ bq, const float* __restrict__ bk, const float* __restrict__ bv)
{
    const int z = blockIdx.z;
    extern __shared__ char smem[];
    const int b = blockIdx.x;
    const int row0 = (z == 2 ? (b >> 5) : (b >> 3)) * 256;
    const int col0 = (z == 2 ? (b & 31) : (b & 7)) * 128;

    ZERO_ACC(acc, 4);

    const float *Ag, *Bg, *bias;
    if (z == 0)      { Ag = g_x;                  Bg = g_wt;             bias = bq; }
    else if (z == 1) { Ag = g_x;                  Bg = g_wt + DIM * DIM; bias = bk; }
    else             { Ag = g_wt + 2 * DIM * DIM; Bg = g_x;              bias = bv; }

    gemm_mainloop<4>(acc, smem, Ag, DIM, row0, Bg, DIM, col0, 0, DIM);

    GEMM_THREAD_COORDS(4);
    float* dst; size_t ld;
    if (z == 0)      { dst = g_q;  ld = DIM; }
    else if (z == 1) { dst = g_k;  ld = DIM; }
    else             { dst = g_vt; ld = SEQ; }

#pragma unroll
    for (int mt = 0; mt < 4; mt++)
#pragma unroll
        for (int h = 0; h < 2; h++) {
            int m = row0 + wm + mt * 16 + r + 8 * h;
            float brow = (z == 2) ? bias[m] : 0.f;
#pragma unroll
            for (int nt = 0; nt < 4; nt++) {
                int n = col0 + wn + nt * 8 + 2 * cc;
                float v0 = acc[mt][nt][2 * h + 0] + ((z == 2) ? brow : bias[n]);
                float v1 = acc[mt][nt][2 * h + 1] + ((z == 2) ? brow : bias[n + 1]);
                float2 w = make_float2(tf32r(v0), tf32r(v1));
                *(float2*)&dst[(size_t)m * ld + n] = w;
            }
        }
}

// ---------------------------------------------------------------------------
// scores: S = SCALE * Q K^T, tiles 256x128; kept iff bj >= 2*bi (272 blocks)
// ---------------------------------------------------------------------------
__global__ __launch_bounds__(512, 1) void gemm_scores_kernel()
{
    int bi = 0, rem = blockIdx.x;
    while (rem >= 32 - 2 * bi) { rem -= 32 - 2 * bi; bi++; }
    const int bj = 2 * bi + rem;

    extern __shared__ char smem[];
    const int row0 = bi * 256, col0 = bj * 128;

    ZERO_ACC(acc, 4);
    gemm_mainloop<4>(acc, smem, g_q, DIM, row0, g_k, DIM, col0, 0, DIM);

    GEMM_THREAD_COORDS(4);
#pragma unroll
    for (int mt = 0; mt < 4; mt++)
#pragma unroll
        for (int h = 0; h < 2; h++) {
            int m = row0 + wm + mt * 16 + r + 8 * h;
#pragma unroll
            for (int nt = 0; nt < 4; nt++) {
                int n = col0 + wn + nt * 8 + 2 * cc;
                float2 w = make_float2(acc[mt][nt][2 * h] * SCALE,
                                       acc[mt][nt][2 * h + 1] * SCALE);
                *(float2*)&g_s[(size_t)m * SEQ + n] = w;
            }
        }
}

// ---------------------------------------------------------------------------
// softmax over j >= i; writes tf32-rounded probs, zero strip in diagonal tile
// ---------------------------------------------------------------------------
__global__ __launch_bounds__(256) void softmax_kernel()
{
    const int i = blockIdx.x;
    const int t = threadIdx.x;
    const float* row = g_s + (size_t)i * SEQ;

    float vals[16];
    float m = -INFINITY;
#pragma unroll
    for (int c = 0; c < 16; c++) {
        int j = t + (c << 8);
        float v = (j >= i) ? row[j] : -INFINITY;
        vals[c] = v;
        m = fmaxf(m, v);
    }
    __shared__ float red[8];
#pragma unroll
    for (int o = 16; o > 0; o >>= 1) m = fmaxf(m, __shfl_xor_sync(0xffffffffu, m, o));
    if ((t & 31) == 0) red[t >> 5] = m;
    __syncthreads();
    float mm = red[0];
#pragma unroll
    for (int w = 1; w < 8; w++) mm = fmaxf(mm, red[w]);
    __syncthreads();

    float sum = 0.f;
#pragma unroll
    for (int c = 0; c < 16; c++) {
        float e = (vals[c] > -INFINITY) ? __expf(vals[c] - mm) : 0.f;
        vals[c] = e;
        sum += e;
    }
#pragma unroll
    for (int o = 16; o > 0; o >>= 1) sum += __shfl_xor_sync(0xffffffffu, sum, o);
    if ((t & 31) == 0) red[t >> 5] = sum;
    __syncthreads();
    float tot = 0.f;
#pragma unroll
    for (int w = 0; w < 8; w++) tot += red[w];
    const float inv = 1.0f / tot;

    const int rowstart = i & ~127;
    float* p = g_p + (size_t)i * SEQ;
#pragma unroll
    for (int c = 0; c < 16; c++) {
        int j = t + (c << 8);
        if (j >= i)             p[j] = tf32r(vals[c] * inv);
        else if (j >= rowstart) p[j] = 0.f;
    }
}

// ---------------------------------------------------------------------------
// PV: read = P @ V ; tiles 128x128 (MT=2); k starts at the diagonal tile.
// grid (8, 32): row0 = y*128 (longest k first), col0 = x*128
// ---------------------------------------------------------------------------
__global__ __launch_bounds__(512, 1) void gemm_pv_kernel(float* __restrict__ out)
{
    extern __shared__ char smem[];
    const int row0 = blockIdx.y * 128, col0 = blockIdx.x * 128;

    ZERO_ACC(acc, 2);
    gemm_mainloop<2>(acc, smem, g_p, SEQ, row0, g_vt, SEQ, col0, row0, SEQ);

    GEMM_THREAD_COORDS(2);
#pragma unroll
    for (int mt = 0; mt < 2; mt++)
#pragma unroll
        for (int h = 0; h < 2; h++) {
            int m = row0 + wm + mt * 16 + r + 8 * h;
#pragma unroll
            for (int nt = 0; nt < 4; nt++) {
                int n = col0 + wn + nt * 8 + 2 * cc;
                float2 w = make_float2(acc[mt][nt][2 * h], acc[mt][nt][2 * h + 1]);
                *(float2*)&out[(size_t)m * OUTD + DIM + n] = w;
            }
        }
}

// ---------------------------------------------------------------------------
// conversions
// ---------------------------------------------------------------------------
__global__ __launch_bounds__(256) void conv_x_kernel(const float* __restrict__ x,
                                                     float* __restrict__ out)
{
    int idx = blockIdx.x * 256 + threadIdx.x;   // float4 index
    int r = idx >> 8;
    int c = (idx & 255) * 4;
    float4 v = *(const float4*)&x[(size_t)r * DIM + c];
    *(float4*)&out[(size_t)r * OUTD + c] = v;   // out[:, 0:1024] = x
    float4 w = make_float4(tf32r(v.x), tf32r(v.y), tf32r(v.z), tf32r(v.w));
    *(float4*)&g_x[(size_t)r * DIM + c] = w;
}

// transpose + tf32-round W [k][n] -> Wt [n][k] (slot z: 0=Q, 1=K, 2=V)
__global__ __launch_bounds__(256) void conv_w_kernel(const float* __restrict__ Wq,
                                                     const float* __restrict__ Wk,
                                                     const float* __restrict__ Wv)
{
    __shared__ float t[32][33];
    const int z = blockIdx.z;
    const float* W = (z == 0) ? Wq : (z == 1) ? Wk : Wv;
    const int n0 = blockIdx.x * 32, k0 = blockIdx.y * 32;
    const int tx = threadIdx.x & 31, ty = threadIdx.x >> 5;
#pragma unroll
    for (int i = 0; i < 4; i++) {
        int k = ty + i * 8;
        t[k][tx] = W[(size_t)(k0 + k) * DIM + n0 + tx];
    }
    __syncthreads();
    float* T = g_wt + (size_t)z * DIM * DIM;
#pragma unroll
    for (int i = 0; i < 4; i++) {
        int n = ty + i * 8;
        T[(size_t)(n0 + n) * DIM + k0 + tx] = tf32r(t[tx][n]);
    }
}

// ---------------------------------------------------------------------------
extern "C" void kernel_launch(void* const* d_in, const int* in_sizes, int n_in,
                              void* d_out, int out_size)
{
    const float* x  = (const float*)d_in[0];
    const float* Wk = (const float*)d_in[1];
    const float* bk = (const float*)d_in[2];
    const float* Wq = (const float*)d_in[3];
    const float* bq = (const float*)d_in[4];
    const float* Wv = (const float*)d_in[5];
    const float* bv = (const float*)d_in[6];
    float* out = (float*)d_out;

    const int SM4 = 2 * (256 * PADW * 4 + BBUF);   // 110592
    const int SM2 = 2 * (128 * PADW * 4 + BBUF);   //  73728

    cudaFuncSetAttribute(gemm_qkv_kernel,    cudaFuncAttributeMaxDynamicSharedMemorySize, SM4);
    cudaFuncSetAttribute(gemm_scores_kernel, cudaFuncAttributeMaxDynamicSharedMemorySize, SM4);
    cudaFuncSetAttribute(gemm_pv_kernel,     cudaFuncAttributeMaxDynamicSharedMemorySize, SM2);

    conv_x_kernel<<<4096, 256>>>(x, out);
    conv_w_kernel<<<dim3(32, 32, 3), 256>>>(Wq, Wk, Wv);
    gemm_qkv_kernel<<<dim3(128, 1, 3), 512, SM4>>>(bq, bk, bv);
    gemm_scores_kernel<<<272, 512, SM4>>>();
    softmax_kernel<<<SEQ, 256>>>();
    gemm_pv_kernel<<<dim3(8, 32), 512, SM2>>>(out);
}